// round 1
// baseline (speedup 1.0000x reference)
#include <cuda_runtime.h>
#include <math.h>

#define N_NODES 50000
#define N_EDGES 500000
#define DIM     128
#define N_REL   51
#define KDIM    1664   // 13*128

// ---------------- scratch (device globals; no allocation allowed) ----------
__device__ int   g_deg[N_NODES];
__device__ int   g_off[N_NODES + 1];
__device__ int   g_fill[N_NODES];
__device__ int   g_esrc[N_EDGES];
__device__ int   g_etype[N_EDGES];
__device__ float g_ew[N_EDGES];
__device__ float g_scaleS[N_NODES];
__device__ float g_ssum;
__device__ float g_x[N_NODES * DIM];
__device__ float g_feats[4 * N_NODES * DIM];   // [feat(4)][node][dim]

// ---------------- preprocessing kernels ------------------------------------
__global__ void k_zero() {
    int i = blockIdx.x * blockDim.x + threadIdx.x;
    if (i < N_NODES) g_deg[i] = 0;
    if (i == 0) g_ssum = 0.0f;
}

__global__ void k_hist(const int* __restrict__ edst) {
    int e = blockIdx.x * blockDim.x + threadIdx.x;
    if (e < N_EDGES) atomicAdd(&g_deg[edst[e]], 1);
}

// single-block exclusive scan over g_deg -> g_off, g_fill
__global__ void k_scan() {
    __shared__ int sh[1024];
    __shared__ int carry;
    int tid = threadIdx.x;
    if (tid == 0) carry = 0;
    __syncthreads();
    for (int base = 0; base < N_NODES; base += 1024) {
        int v = (base + tid < N_NODES) ? g_deg[base + tid] : 0;
        int x = v;
        for (int off = 1; off < 1024; off <<= 1) {
            sh[tid] = x;
            __syncthreads();
            int y = (tid >= off) ? sh[tid - off] : 0;
            __syncthreads();
            x += y;
        }
        int excl = carry + x - v;
        if (base + tid < N_NODES) {
            g_off[base + tid]  = excl;
            g_fill[base + tid] = excl;
        }
        __syncthreads();
        if (tid == 1023) carry += x;
        __syncthreads();
    }
    if (tid == 0) g_off[N_NODES] = carry;   // == N_EDGES
}

__global__ void k_logsum() {
    __shared__ float sh[256];
    int i = blockIdx.x * blockDim.x + threadIdx.x;
    float v = (i < N_NODES) ? logf((float)g_deg[i] + 1.0f) : 0.0f;
    sh[threadIdx.x] = v;
    __syncthreads();
    for (int s = 128; s > 0; s >>= 1) {
        if (threadIdx.x < s) sh[threadIdx.x] += sh[threadIdx.x + s];
        __syncthreads();
    }
    if (threadIdx.x == 0) atomicAdd(&g_ssum, sh[0]);
}

__global__ void k_scale() {
    int i = blockIdx.x * blockDim.x + threadIdx.x;
    if (i < N_NODES)
        g_scaleS[i] = logf((float)g_deg[i] + 1.0f) * ((float)N_NODES / g_ssum);
}

__global__ void k_fill(const int* __restrict__ esrc, const int* __restrict__ edst,
                       const int* __restrict__ etype, const float* __restrict__ ew) {
    int e = blockIdx.x * blockDim.x + threadIdx.x;
    if (e >= N_EDGES) return;
    int d = edst[e];
    int p = atomicAdd(&g_fill[d], 1);
    g_esrc[p]  = esrc[e];
    g_etype[p] = etype[e];
    g_ew[p]    = ew[e];
}

__global__ void k_copyx(const float* __restrict__ x0) {
    int i = blockIdx.x * blockDim.x + threadIdx.x;
    int n4 = N_NODES * DIM / 4;
    if (i < n4)
        reinterpret_cast<float4*>(g_x)[i] = reinterpret_cast<const float4*>(x0)[i];
}

// ---------------- per-layer aggregation (warp per node) --------------------
__global__ void k_agg(const float* __restrict__ x0, const float* __restrict__ relw) {
    int gw   = (blockIdx.x * blockDim.x + threadIdx.x) >> 5;
    int lane = threadIdx.x & 31;
    if (gw >= N_NODES) return;
    int beg = g_off[gw], end = g_off[gw + 1];

    float4 vs  = make_float4(0.f, 0.f, 0.f, 0.f);
    float4 vq  = make_float4(0.f, 0.f, 0.f, 0.f);
    float4 vmx = make_float4(-INFINITY, -INFINITY, -INFINITY, -INFINITY);
    float4 vmn = make_float4( INFINITY,  INFINITY,  INFINITY,  INFINITY);

    const float4* xv = reinterpret_cast<const float4*>(g_x);
    const float4* rv = reinterpret_cast<const float4*>(relw);

    for (int e = beg; e < end; e++) {
        int   s = __ldg(g_esrc + e);
        int   t = __ldg(g_etype + e);
        float w = __ldg(g_ew + e);
        float4 a = __ldg(xv + s * 32 + lane);
        float4 r = __ldg(rv + t * 32 + lane);
        float mx = a.x * r.x * w, my = a.y * r.y * w, mz = a.z * r.z * w, mw = a.w * r.w * w;
        vs.x += mx; vs.y += my; vs.z += mz; vs.w += mw;
        vq.x += mx * mx; vq.y += my * my; vq.z += mz * mz; vq.w += mw * mw;
        vmx.x = fmaxf(vmx.x, mx); vmx.y = fmaxf(vmx.y, my);
        vmx.z = fmaxf(vmx.z, mz); vmx.w = fmaxf(vmx.w, mw);
        vmn.x = fminf(vmn.x, mx); vmn.y = fminf(vmn.y, my);
        vmn.z = fminf(vmn.z, mz); vmn.w = fminf(vmn.w, mw);
    }

    // boundary self-message x0
    float4 b = __ldg(reinterpret_cast<const float4*>(x0) + gw * 32 + lane);
    vs.x += b.x; vs.y += b.y; vs.z += b.z; vs.w += b.w;
    vq.x += b.x * b.x; vq.y += b.y * b.y; vq.z += b.z * b.z; vq.w += b.w * b.w;
    vmx.x = fmaxf(vmx.x, b.x); vmx.y = fmaxf(vmx.y, b.y);
    vmx.z = fmaxf(vmx.z, b.z); vmx.w = fmaxf(vmx.w, b.w);
    vmn.x = fminf(vmn.x, b.x); vmn.y = fminf(vmn.y, b.y);
    vmn.z = fminf(vmn.z, b.z); vmn.w = fminf(vmn.w, b.w);

    float dinv = 1.0f / ((float)(end - beg) + 1.0f);
    float4 mean = make_float4(vs.x * dinv, vs.y * dinv, vs.z * dinv, vs.w * dinv);
    float4 sqm  = make_float4(vq.x * dinv, vq.y * dinv, vq.z * dinv, vq.w * dinv);
    float4 stdv;
    stdv.x = sqrtf(fmaxf(sqm.x - mean.x * mean.x, 1e-6f));
    stdv.y = sqrtf(fmaxf(sqm.y - mean.y * mean.y, 1e-6f));
    stdv.z = sqrtf(fmaxf(sqm.z - mean.z * mean.z, 1e-6f));
    stdv.w = sqrtf(fmaxf(sqm.w - mean.w * mean.w, 1e-6f));

    float4* f = reinterpret_cast<float4*>(g_feats);
    f[(0 * N_NODES + gw) * 32 + lane] = mean;
    f[(1 * N_NODES + gw) * 32 + lane] = vmx;
    f[(2 * N_NODES + gw) * 32 + lane] = vmn;
    f[(3 * N_NODES + gw) * 32 + lane] = stdv;
}

// ---------------- fused GEMM + LayerNorm + ReLU + residual -----------------
// C[50000,128] = A[50000,1664] @ W[1664,128]; A built on the fly:
//   k-block b (0..12): b<12 -> s_{b/4}(n) * feats[b%4][n][k%128];  b==12 -> x[n][k%128]
__global__ void __launch_bounds__(256)
k_gemm(const float* __restrict__ W, const float* __restrict__ bias,
       const float* __restrict__ lng, const float* __restrict__ lnb) {
    __shared__ float As[8][132];
    __shared__ float Bs[8][128];

    int tid = threadIdx.x;
    int tx = tid & 15, ty = tid >> 4;
    int row0 = blockIdx.x * 128;

    int arow  = tid >> 1;
    int apart = (tid & 1) * 4;
    int brow  = tid >> 5;           // 0..7
    int bcol  = (tid & 31) * 4;
    int grow  = row0 + arow;
    bool rok  = grow < N_NODES;

    float acc[8][8];
#pragma unroll
    for (int i = 0; i < 8; i++)
#pragma unroll
        for (int j = 0; j < 8; j++) acc[i][j] = 0.0f;

    for (int kt = 0; kt < KDIM / 8; kt++) {
        int kb   = kt * 8;
        int bblk = kb >> 7;                 // 0..12, uniform per iteration
        int kc   = (kb & 127) + apart;

        float4 av = make_float4(0.f, 0.f, 0.f, 0.f);
        if (rok) {
            if (bblk < 12) {
                int jj = bblk >> 2, ff = bblk & 3;
                av = *reinterpret_cast<const float4*>(
                    g_feats + (ff * N_NODES + grow) * 128 + kc);
                float s = g_scaleS[grow];
                float fac = (jj == 0) ? 1.0f : ((jj == 1) ? s : 1.0f / fmaxf(s, 1e-2f));
                av.x *= fac; av.y *= fac; av.z *= fac; av.w *= fac;
            } else {
                av = *reinterpret_cast<const float4*>(g_x + grow * 128 + kc);
            }
        }
        float4 bv = *reinterpret_cast<const float4*>(W + (kb + brow) * 128 + bcol);

        __syncthreads();
        As[apart + 0][arow] = av.x;
        As[apart + 1][arow] = av.y;
        As[apart + 2][arow] = av.z;
        As[apart + 3][arow] = av.w;
        *reinterpret_cast<float4*>(&Bs[brow][bcol]) = bv;
        __syncthreads();

#pragma unroll
        for (int kk = 0; kk < 8; kk++) {
            float a[8], bb[8];
            float4 a0 = *reinterpret_cast<const float4*>(&As[kk][ty * 8]);
            float4 a1 = *reinterpret_cast<const float4*>(&As[kk][ty * 8 + 4]);
            float4 b0 = *reinterpret_cast<const float4*>(&Bs[kk][tx * 8]);
            float4 b1 = *reinterpret_cast<const float4*>(&Bs[kk][tx * 8 + 4]);
            a[0]=a0.x; a[1]=a0.y; a[2]=a0.z; a[3]=a0.w;
            a[4]=a1.x; a[5]=a1.y; a[6]=a1.z; a[7]=a1.w;
            bb[0]=b0.x; bb[1]=b0.y; bb[2]=b0.z; bb[3]=b0.w;
            bb[4]=b1.x; bb[5]=b1.y; bb[6]=b1.z; bb[7]=b1.w;
#pragma unroll
            for (int i = 0; i < 8; i++)
#pragma unroll
                for (int j = 0; j < 8; j++) acc[i][j] += a[i] * bb[j];
        }
    }
    __syncthreads();

    // epilogue: bias + LayerNorm (row = 16 consecutive lanes) + ReLU + residual
#pragma unroll
    for (int i = 0; i < 8; i++) {
        int r = row0 + ty * 8 + i;
        float v[8];
        float lsum = 0.f, lsq = 0.f;
#pragma unroll
        for (int j = 0; j < 8; j++) {
            v[j] = acc[i][j] + __ldg(bias + tx * 8 + j);
            lsum += v[j];
            lsq  += v[j] * v[j];
        }
#pragma unroll
        for (int m = 1; m < 16; m <<= 1) {
            lsum += __shfl_xor_sync(0xffffffffu, lsum, m);
            lsq  += __shfl_xor_sync(0xffffffffu, lsq,  m);
        }
        float mu   = lsum * (1.0f / 128.0f);
        float var  = lsq * (1.0f / 128.0f) - mu * mu;
        float rstd = rsqrtf(var + 1e-5f);
        if (r < N_NODES) {
#pragma unroll
            for (int j = 0; j < 8; j++) {
                int c = tx * 8 + j;
                float o = (v[j] - mu) * rstd * __ldg(lng + c) + __ldg(lnb + c);
                o = fmaxf(o, 0.0f);
                g_x[r * 128 + c] = o + g_x[r * 128 + c];
            }
        }
    }
}

// ---------------- distmult scoring (warp per triple) ------------------------
__global__ void k_score(const int* __restrict__ src, const int* __restrict__ rel,
                        const int* __restrict__ dst, const float* __restrict__ qw,
                        float* __restrict__ out) {
    int gw   = (blockIdx.x * blockDim.x + threadIdx.x) >> 5;
    int lane = threadIdx.x & 31;
    if (gw >= 1024 * 32) return;
    int s = __ldg(src + gw), r = __ldg(rel + gw), d = __ldg(dst + gw);
    const float4* xv = reinterpret_cast<const float4*>(g_x);
    float4 a = __ldg(xv + s * 32 + lane);
    float4 q = __ldg(reinterpret_cast<const float4*>(qw) + r * 32 + lane);
    float4 c = __ldg(xv + d * 32 + lane);
    float p = a.x * q.x * c.x + a.y * q.y * c.y + a.z * q.z * c.z + a.w * q.w * c.w;
#pragma unroll
    for (int m = 16; m > 0; m >>= 1) p += __shfl_xor_sync(0xffffffffu, p, m);
    if (lane == 0) out[gw] = p;
}

// ---------------- launcher ---------------------------------------------------
extern "C" void kernel_launch(void* const* d_in, const int* in_sizes, int n_in,
                              void* d_out, int out_size) {
    const float* x0    = (const float*)d_in[0];
    const int*   eidx  = (const int*)  d_in[1];
    const int*   etype = (const int*)  d_in[2];
    const float* ew    = (const float*)d_in[3];
    const float* relw  = (const float*)d_in[4];
    const float* linw  = (const float*)d_in[5];
    const float* linb  = (const float*)d_in[6];
    const float* lng   = (const float*)d_in[7];
    const float* lnb   = (const float*)d_in[8];
    const float* qw    = (const float*)d_in[9];
    const int*   src   = (const int*)  d_in[10];
    const int*   rel   = (const int*)  d_in[11];
    const int*   dst   = (const int*)  d_in[12];
    float*       out   = (float*)d_out;

    const int* esrc = eidx;
    const int* edst = eidx + N_EDGES;

    k_zero<<<(N_NODES + 255) / 256, 256>>>();
    k_hist<<<(N_EDGES + 255) / 256, 256>>>(edst);
    k_scan<<<1, 1024>>>();
    k_logsum<<<(N_NODES + 255) / 256, 256>>>();
    k_scale<<<(N_NODES + 255) / 256, 256>>>();
    k_fill<<<(N_EDGES + 255) / 256, 256>>>(esrc, edst, etype, ew);
    k_copyx<<<(N_NODES * DIM / 4 + 255) / 256, 256>>>(x0);

    for (int l = 0; l < 4; l++) {
        k_agg<<<(N_NODES * 32 + 255) / 256, 256>>>(x0, relw + l * N_REL * DIM);
        k_gemm<<<(N_NODES + 127) / 128, 256>>>(linw + l * KDIM * DIM,
                                               linb + l * DIM,
                                               lng + l * DIM,
                                               lnb + l * DIM);
    }

    k_score<<<(1024 * 32 * 32 + 255) / 256, 256>>>(src, rel, dst, qw, out);
}

// round 2
// speedup vs baseline: 1.0814x; 1.0814x over previous
#include <cuda_runtime.h>
#include <math.h>

#define N_NODES 50000
#define N_EDGES 500000
#define DIM     128
#define N_REL   51
#define KDIM    1664   // 13*128
#define BK      16
#define NKT     (KDIM / BK)   // 104

// ---------------- scratch (device globals; no allocation allowed) ----------
__device__ int   g_deg[N_NODES];
__device__ int   g_off[N_NODES + 1];
__device__ int   g_fill[N_NODES];
__device__ int   g_esrc[N_EDGES];
__device__ int   g_etype[N_EDGES];
__device__ float g_ew[N_EDGES];
__device__ float g_scaleS[N_NODES];
__device__ float g_x[N_NODES * DIM];
__device__ float g_feats[4 * N_NODES * DIM];   // [feat(4)][node][dim]

// ---------------- preprocessing kernels ------------------------------------
__global__ void k_zero() {
    int i = blockIdx.x * blockDim.x + threadIdx.x;
    if (i < N_NODES) g_deg[i] = 0;
}

__global__ void k_hist(const int* __restrict__ edst) {
    int e = blockIdx.x * blockDim.x + threadIdx.x;
    if (e < N_EDGES) atomicAdd(&g_deg[edst[e]], 1);
}

// single-block: exclusive scan (offsets) + log-degree scale (fused)
__global__ void k_scan() {
    __shared__ int   wsum[32];
    __shared__ int   carry_sh;
    __shared__ float fred[32];
    __shared__ float ssum_sh;
    int tid  = threadIdx.x;
    int lane = tid & 31, wid = tid >> 5;
    if (tid == 0) carry_sh = 0;
    __syncthreads();

    for (int base = 0; base < N_NODES; base += 1024) {
        int v = (base + tid < N_NODES) ? g_deg[base + tid] : 0;
        // warp inclusive scan
        int x = v;
#pragma unroll
        for (int off = 1; off < 32; off <<= 1) {
            int y = __shfl_up_sync(0xffffffffu, x, off);
            if (lane >= off) x += y;
        }
        if (lane == 31) wsum[wid] = x;
        __syncthreads();
        if (wid == 0) {
            int w = (lane < 32) ? wsum[lane] : 0;
#pragma unroll
            for (int off = 1; off < 32; off <<= 1) {
                int y = __shfl_up_sync(0xffffffffu, w, off);
                if (lane >= off) w += y;
            }
            wsum[lane] = w;
        }
        __syncthreads();
        int wpre = (wid > 0) ? wsum[wid - 1] : 0;
        int excl = carry_sh + wpre + x - v;
        if (base + tid < N_NODES) {
            g_off[base + tid]  = excl;
            g_fill[base + tid] = excl;
        }
        __syncthreads();
        if (tid == 1023) carry_sh += wpre + x;   // total of this chunk
        __syncthreads();
    }
    if (tid == 0) g_off[N_NODES] = carry_sh;

    // fused: sum of log(deg+1)
    float ls = 0.0f;
    for (int i = tid; i < N_NODES; i += 1024)
        ls += logf((float)g_deg[i] + 1.0f);
#pragma unroll
    for (int m = 16; m > 0; m >>= 1) ls += __shfl_xor_sync(0xffffffffu, ls, m);
    if (lane == 0) fred[wid] = ls;
    __syncthreads();
    if (wid == 0) {
        float s = (lane < 32) ? fred[lane] : 0.0f;
#pragma unroll
        for (int m = 16; m > 0; m >>= 1) s += __shfl_xor_sync(0xffffffffu, s, m);
        if (lane == 0) ssum_sh = s;
    }
    __syncthreads();
    float inv_mean = (float)N_NODES / ssum_sh;
    for (int i = tid; i < N_NODES; i += 1024)
        g_scaleS[i] = logf((float)g_deg[i] + 1.0f) * inv_mean;
}

__global__ void k_fill(const int* __restrict__ esrc, const int* __restrict__ edst,
                       const int* __restrict__ etype, const float* __restrict__ ew) {
    int e = blockIdx.x * blockDim.x + threadIdx.x;
    if (e >= N_EDGES) return;
    int d = edst[e];
    int p = atomicAdd(&g_fill[d], 1);
    g_esrc[p]  = esrc[e];
    g_etype[p] = etype[e];
    g_ew[p]    = ew[e];
}

// ---------------- per-layer aggregation (warp per node) --------------------
__global__ void k_agg(const float* __restrict__ xin, const float* __restrict__ x0,
                      const float* __restrict__ relw) {
    int gw   = (blockIdx.x * blockDim.x + threadIdx.x) >> 5;
    int lane = threadIdx.x & 31;
    if (gw >= N_NODES) return;
    int beg = g_off[gw], end = g_off[gw + 1];

    float4 vs  = make_float4(0.f, 0.f, 0.f, 0.f);
    float4 vq  = make_float4(0.f, 0.f, 0.f, 0.f);
    float4 vmx = make_float4(-INFINITY, -INFINITY, -INFINITY, -INFINITY);
    float4 vmn = make_float4( INFINITY,  INFINITY,  INFINITY,  INFINITY);

    const float4* xv = reinterpret_cast<const float4*>(xin);
    const float4* rv = reinterpret_cast<const float4*>(relw);

    for (int e = beg; e < end; e++) {
        int   s = __ldg(g_esrc + e);
        int   t = __ldg(g_etype + e);
        float w = __ldg(g_ew + e);
        float4 a = __ldg(xv + s * 32 + lane);
        float4 r = __ldg(rv + t * 32 + lane);
        float mx = a.x * r.x * w, my = a.y * r.y * w, mz = a.z * r.z * w, mw = a.w * r.w * w;
        vs.x += mx; vs.y += my; vs.z += mz; vs.w += mw;
        vq.x += mx * mx; vq.y += my * my; vq.z += mz * mz; vq.w += mw * mw;
        vmx.x = fmaxf(vmx.x, mx); vmx.y = fmaxf(vmx.y, my);
        vmx.z = fmaxf(vmx.z, mz); vmx.w = fmaxf(vmx.w, mw);
        vmn.x = fminf(vmn.x, mx); vmn.y = fminf(vmn.y, my);
        vmn.z = fminf(vmn.z, mz); vmn.w = fminf(vmn.w, mw);
    }

    // boundary self-message x0
    float4 b = __ldg(reinterpret_cast<const float4*>(x0) + gw * 32 + lane);
    vs.x += b.x; vs.y += b.y; vs.z += b.z; vs.w += b.w;
    vq.x += b.x * b.x; vq.y += b.y * b.y; vq.z += b.z * b.z; vq.w += b.w * b.w;
    vmx.x = fmaxf(vmx.x, b.x); vmx.y = fmaxf(vmx.y, b.y);
    vmx.z = fmaxf(vmx.z, b.z); vmx.w = fmaxf(vmx.w, b.w);
    vmn.x = fminf(vmn.x, b.x); vmn.y = fminf(vmn.y, b.y);
    vmn.z = fminf(vmn.z, b.z); vmn.w = fminf(vmn.w, b.w);

    float dinv = 1.0f / ((float)(end - beg) + 1.0f);
    float4 mean = make_float4(vs.x * dinv, vs.y * dinv, vs.z * dinv, vs.w * dinv);
    float4 sqm  = make_float4(vq.x * dinv, vq.y * dinv, vq.z * dinv, vq.w * dinv);
    float4 stdv;
    stdv.x = sqrtf(fmaxf(sqm.x - mean.x * mean.x, 1e-6f));
    stdv.y = sqrtf(fmaxf(sqm.y - mean.y * mean.y, 1e-6f));
    stdv.z = sqrtf(fmaxf(sqm.z - mean.z * mean.z, 1e-6f));
    stdv.w = sqrtf(fmaxf(sqm.w - mean.w * mean.w, 1e-6f));

    float4* f = reinterpret_cast<float4*>(g_feats);
    f[(0 * N_NODES + gw) * 32 + lane] = mean;
    f[(1 * N_NODES + gw) * 32 + lane] = vmx;
    f[(2 * N_NODES + gw) * 32 + lane] = vmn;
    f[(3 * N_NODES + gw) * 32 + lane] = stdv;
}

// ---------------- fused GEMM + LayerNorm + ReLU + residual -----------------
// C[50000,128] = A[50000,1664] @ W[1664,128]; A built on the fly.
// Double-buffered SMEM, BK=16, one __syncthreads per K-step.
__global__ void __launch_bounds__(256, 2)
k_gemm(const float* __restrict__ W, const float* __restrict__ bias,
       const float* __restrict__ lng, const float* __restrict__ lnb,
       const float* __restrict__ xin) {
    __shared__ float As[2][BK][132];
    __shared__ float Bs[2][BK][128];

    int tid = threadIdx.x;
    int tx = tid & 15, ty = tid >> 4;
    int row0 = blockIdx.x * 128;

    // A loader: thread -> (row am, k-half ak)
    int am = tid >> 1;
    int ak = (tid & 1) * 8;
    int grow = row0 + am;
    bool rok = grow < N_NODES;
    float sS = rok ? g_scaleS[grow] : 1.0f;
    float fac1 = sS;
    float fac2 = 1.0f / fmaxf(sS, 1e-2f);
    // B loader: thread -> (k-row bk, col bn)
    int bk = tid >> 4;
    int bn = (tid & 15) * 8;

    float acc[8][8];
#pragma unroll
    for (int i = 0; i < 8; i++)
#pragma unroll
        for (int j = 0; j < 8; j++) acc[i][j] = 0.0f;

    float4 ra0, ra1, rb0, rb1;

    // --- tile loader (to registers) ---
    auto load_tile = [&](int kt) {
        int kb   = kt * BK;
        int bblk = kb >> 7;             // 0..12, uniform
        int kc   = (kb & 127) + ak;
        if (rok) {
            const float* p;
            float fac;
            if (bblk < 12) {
                int jj = bblk >> 2, ff = bblk & 3;
                p   = g_feats + (ff * N_NODES + grow) * 128 + kc;
                fac = (jj == 0) ? 1.0f : ((jj == 1) ? fac1 : fac2);
            } else {
                p   = xin + grow * 128 + kc;
                fac = 1.0f;
            }
            ra0 = *reinterpret_cast<const float4*>(p);
            ra1 = *reinterpret_cast<const float4*>(p + 4);
            ra0.x *= fac; ra0.y *= fac; ra0.z *= fac; ra0.w *= fac;
            ra1.x *= fac; ra1.y *= fac; ra1.z *= fac; ra1.w *= fac;
        } else {
            ra0 = make_float4(0.f, 0.f, 0.f, 0.f);
            ra1 = ra0;
        }
        const float* wp = W + (kb + bk) * 128 + bn;
        rb0 = *reinterpret_cast<const float4*>(wp);
        rb1 = *reinterpret_cast<const float4*>(wp + 4);
    };

    auto store_tile = [&](int buf) {
        As[buf][ak + 0][am] = ra0.x;
        As[buf][ak + 1][am] = ra0.y;
        As[buf][ak + 2][am] = ra0.z;
        As[buf][ak + 3][am] = ra0.w;
        As[buf][ak + 4][am] = ra1.x;
        As[buf][ak + 5][am] = ra1.y;
        As[buf][ak + 6][am] = ra1.z;
        As[buf][ak + 7][am] = ra1.w;
        *reinterpret_cast<float4*>(&Bs[buf][bk][bn])     = rb0;
        *reinterpret_cast<float4*>(&Bs[buf][bk][bn + 4]) = rb1;
    };

    load_tile(0);
    store_tile(0);
    __syncthreads();

#pragma unroll 1
    for (int kt = 0; kt < NKT; kt++) {
        if (kt + 1 < NKT) load_tile(kt + 1);
        int buf = kt & 1;
#pragma unroll
        for (int kk = 0; kk < BK; kk++) {
            float4 a0 = *reinterpret_cast<const float4*>(&As[buf][kk][ty * 8]);
            float4 a1 = *reinterpret_cast<const float4*>(&As[buf][kk][ty * 8 + 4]);
            float4 b0 = *reinterpret_cast<const float4*>(&Bs[buf][kk][tx * 8]);
            float4 b1 = *reinterpret_cast<const float4*>(&Bs[buf][kk][tx * 8 + 4]);
            float a[8] = {a0.x, a0.y, a0.z, a0.w, a1.x, a1.y, a1.z, a1.w};
            float b[8] = {b0.x, b0.y, b0.z, b0.w, b1.x, b1.y, b1.z, b1.w};
#pragma unroll
            for (int i = 0; i < 8; i++)
#pragma unroll
                for (int j = 0; j < 8; j++) acc[i][j] += a[i] * b[j];
        }
        if (kt + 1 < NKT) {
            store_tile((kt + 1) & 1);
            __syncthreads();
        }
    }

    // epilogue: bias + LayerNorm (row = 16 consecutive lanes) + ReLU + residual
#pragma unroll
    for (int i = 0; i < 8; i++) {
        int r = row0 + ty * 8 + i;
        float v[8];
        float lsum = 0.f, lsq = 0.f;
#pragma unroll
        for (int j = 0; j < 8; j++) {
            v[j] = acc[i][j] + __ldg(bias + tx * 8 + j);
            lsum += v[j];
            lsq  += v[j] * v[j];
        }
#pragma unroll
        for (int m = 1; m < 16; m <<= 1) {
            lsum += __shfl_xor_sync(0xffffffffu, lsum, m);
            lsq  += __shfl_xor_sync(0xffffffffu, lsq,  m);
        }
        float mu   = lsum * (1.0f / 128.0f);
        float var  = lsq * (1.0f / 128.0f) - mu * mu;
        float rstd = rsqrtf(var + 1e-5f);
        if (r < N_NODES) {
#pragma unroll
            for (int j = 0; j < 8; j++) {
                int c = tx * 8 + j;
                float o = (v[j] - mu) * rstd * __ldg(lng + c) + __ldg(lnb + c);
                o = fmaxf(o, 0.0f);
                g_x[r * 128 + c] = o + xin[r * 128 + c];
            }
        }
    }
}

// ---------------- distmult scoring (warp per triple) ------------------------
__global__ void k_score(const int* __restrict__ src, const int* __restrict__ rel,
                        const int* __restrict__ dst, const float* __restrict__ qw,
                        float* __restrict__ out) {
    int gw   = (blockIdx.x * blockDim.x + threadIdx.x) >> 5;
    int lane = threadIdx.x & 31;
    if (gw >= 1024 * 32) return;
    int s = __ldg(src + gw), r = __ldg(rel + gw), d = __ldg(dst + gw);
    const float4* xv = reinterpret_cast<const float4*>(g_x);
    float4 a = __ldg(xv + s * 32 + lane);
    float4 q = __ldg(reinterpret_cast<const float4*>(qw) + r * 32 + lane);
    float4 c = __ldg(xv + d * 32 + lane);
    float p = a.x * q.x * c.x + a.y * q.y * c.y + a.z * q.z * c.z + a.w * q.w * c.w;
#pragma unroll
    for (int m = 16; m > 0; m >>= 1) p += __shfl_xor_sync(0xffffffffu, p, m);
    if (lane == 0) out[gw] = p;
}

// ---------------- launcher ---------------------------------------------------
extern "C" void kernel_launch(void* const* d_in, const int* in_sizes, int n_in,
                              void* d_out, int out_size) {
    const float* x0    = (const float*)d_in[0];
    const int*   eidx  = (const int*)  d_in[1];
    const int*   etype = (const int*)  d_in[2];
    const float* ew    = (const float*)d_in[3];
    const float* relw  = (const float*)d_in[4];
    const float* linw  = (const float*)d_in[5];
    const float* linb  = (const float*)d_in[6];
    const float* lng   = (const float*)d_in[7];
    const float* lnb   = (const float*)d_in[8];
    const float* qw    = (const float*)d_in[9];
    const int*   src   = (const int*)  d_in[10];
    const int*   rel   = (const int*)  d_in[11];
    const int*   dst   = (const int*)  d_in[12];
    float*       out   = (float*)d_out;

    const int* esrc = eidx;
    const int* edst = eidx + N_EDGES;

    float* gx;
    cudaGetSymbolAddress((void**)&gx, g_x);

    k_zero<<<(N_NODES + 255) / 256, 256>>>();
    k_hist<<<(N_EDGES + 255) / 256, 256>>>(edst);
    k_scan<<<1, 1024>>>();
    k_fill<<<(N_EDGES + 255) / 256, 256>>>(esrc, edst, etype, ew);

    for (int l = 0; l < 4; l++) {
        const float* xin = (l == 0) ? x0 : gx;
        k_agg<<<(N_NODES * 32 + 255) / 256, 256>>>(xin, x0, relw + l * N_REL * DIM);
        k_gemm<<<(N_NODES + 127) / 128, 256>>>(linw + l * KDIM * DIM,
                                               linb + l * DIM,
                                               lng + l * DIM,
                                               lnb + l * DIM,
                                               xin);
    }

    k_score<<<(1024 * 32 * 32 + 255) / 256, 256>>>(src, rel, dst, qw, out);
}

// round 5
// speedup vs baseline: 2.7364x; 2.5304x over previous
#include <cuda_runtime.h>
#include <stdint.h>
#include <math.h>

#define N_NODES 50000
#define N_EDGES 500000
#define DIM     128
#define N_REL   51
#define KDIM    1664   // 13*128
#define BK      16
#define NKT     (KDIM / BK)   // 104
#define ASTR    24
#define BSTR    136

// ---------------- scratch (device globals; no allocation allowed) ----------
__device__ int   g_deg[N_NODES];
__device__ int   g_off[N_NODES + 1];
__device__ int   g_fill[N_NODES];
__device__ int   g_esrc[N_EDGES];
__device__ int   g_etype[N_EDGES];
__device__ float g_ew[N_EDGES];
__device__ float g_scaleS[N_NODES];
__device__ float g_x[N_NODES * DIM];
__device__ float g_feats[4 * N_NODES * DIM];   // [feat(4)][node][dim]
__device__ float g_W[4 * KDIM * DIM];          // tf32-rounded weights

// ---------------- helpers ----------------------------------------------------
__device__ __forceinline__ float f2tf(float f) {
    uint32_t u;
    asm("cvt.rna.tf32.f32 %0, %1;" : "=r"(u) : "f"(f));
    return __uint_as_float(u);
}

// ---------------- preprocessing kernels ------------------------------------
__global__ void k_cvtW(const float* __restrict__ linw) {
    int i = blockIdx.x * blockDim.x + threadIdx.x;
    if (i < 4 * KDIM * DIM) g_W[i] = f2tf(linw[i]);
}

__global__ void k_zero() {
    int i = blockIdx.x * blockDim.x + threadIdx.x;
    if (i < N_NODES) g_deg[i] = 0;
}

__global__ void k_hist(const int* __restrict__ edst) {
    int e = blockIdx.x * blockDim.x + threadIdx.x;
    if (e < N_EDGES) atomicAdd(&g_deg[edst[e]], 1);
}

// single-block: exclusive scan (offsets) + log-degree scale (fused)
__global__ void k_scan() {
    __shared__ int   wsum[32];
    __shared__ int   carry_sh;
    __shared__ float fred[32];
    __shared__ float ssum_sh;
    int tid  = threadIdx.x;
    int lane = tid & 31, wid = tid >> 5;
    if (tid == 0) carry_sh = 0;
    __syncthreads();

    for (int base = 0; base < N_NODES; base += 1024) {
        int v = (base + tid < N_NODES) ? g_deg[base + tid] : 0;
        int x = v;
#pragma unroll
        for (int off = 1; off < 32; off <<= 1) {
            int y = __shfl_up_sync(0xffffffffu, x, off);
            if (lane >= off) x += y;
        }
        if (lane == 31) wsum[wid] = x;
        __syncthreads();
        if (wid == 0) {
            int w = (lane < 32) ? wsum[lane] : 0;
#pragma unroll
            for (int off = 1; off < 32; off <<= 1) {
                int y = __shfl_up_sync(0xffffffffu, w, off);
                if (lane >= off) w += y;
            }
            wsum[lane] = w;
        }
        __syncthreads();
        int wpre = (wid > 0) ? wsum[wid - 1] : 0;
        int excl = carry_sh + wpre + x - v;
        if (base + tid < N_NODES) {
            g_off[base + tid]  = excl;
            g_fill[base + tid] = excl;
        }
        __syncthreads();
        if (tid == 1023) carry_sh += wpre + x;
        __syncthreads();
    }
    if (tid == 0) g_off[N_NODES] = carry_sh;

    float ls = 0.0f;
    for (int i = tid; i < N_NODES; i += 1024)
        ls += logf((float)g_deg[i] + 1.0f);
#pragma unroll
    for (int m = 16; m > 0; m >>= 1) ls += __shfl_xor_sync(0xffffffffu, ls, m);
    if (lane == 0) fred[wid] = ls;
    __syncthreads();
    if (wid == 0) {
        float s = (lane < 32) ? fred[lane] : 0.0f;
#pragma unroll
        for (int m = 16; m > 0; m >>= 1) s += __shfl_xor_sync(0xffffffffu, s, m);
        if (lane == 0) ssum_sh = s;
    }
    __syncthreads();
    float inv_mean = (float)N_NODES / ssum_sh;
    for (int i = tid; i < N_NODES; i += 1024)
        g_scaleS[i] = logf((float)g_deg[i] + 1.0f) * inv_mean;
}

__global__ void k_fill(const int* __restrict__ esrc, const int* __restrict__ edst,
                       const int* __restrict__ etype, const float* __restrict__ ew) {
    int e = blockIdx.x * blockDim.x + threadIdx.x;
    if (e >= N_EDGES) return;
    int d = edst[e];
    int p = atomicAdd(&g_fill[d], 1);
    g_esrc[p]  = esrc[e];
    g_etype[p] = etype[e];
    g_ew[p]    = ew[e];
}

// ---------------- per-layer aggregation (warp per node) --------------------
__global__ void k_agg(const float* __restrict__ xin, const float* __restrict__ x0,
                      const float* __restrict__ relw) {
    int gw   = (blockIdx.x * blockDim.x + threadIdx.x) >> 5;
    int lane = threadIdx.x & 31;
    if (gw >= N_NODES) return;
    int beg = g_off[gw], end = g_off[gw + 1];

    float4 vs  = make_float4(0.f, 0.f, 0.f, 0.f);
    float4 vq  = make_float4(0.f, 0.f, 0.f, 0.f);
    float4 vmx = make_float4(-INFINITY, -INFINITY, -INFINITY, -INFINITY);
    float4 vmn = make_float4( INFINITY,  INFINITY,  INFINITY,  INFINITY);

    const float4* xv = reinterpret_cast<const float4*>(xin);
    const float4* rv = reinterpret_cast<const float4*>(relw);

    for (int e = beg; e < end; e++) {
        int   s = __ldg(g_esrc + e);
        int   t = __ldg(g_etype + e);
        float w = __ldg(g_ew + e);
        float4 a = __ldg(xv + s * 32 + lane);
        float4 r = __ldg(rv + t * 32 + lane);
        float mx = a.x * r.x * w, my = a.y * r.y * w, mz = a.z * r.z * w, mw = a.w * r.w * w;
        vs.x += mx; vs.y += my; vs.z += mz; vs.w += mw;
        vq.x += mx * mx; vq.y += my * my; vq.z += mz * mz; vq.w += mw * mw;
        vmx.x = fmaxf(vmx.x, mx); vmx.y = fmaxf(vmx.y, my);
        vmx.z = fmaxf(vmx.z, mz); vmx.w = fmaxf(vmx.w, mw);
        vmn.x = fminf(vmn.x, mx); vmn.y = fminf(vmn.y, my);
        vmn.z = fminf(vmn.z, mz); vmn.w = fminf(vmn.w, mw);
    }

    float4 b = __ldg(reinterpret_cast<const float4*>(x0) + gw * 32 + lane);
    vs.x += b.x; vs.y += b.y; vs.z += b.z; vs.w += b.w;
    vq.x += b.x * b.x; vq.y += b.y * b.y; vq.z += b.z * b.z; vq.w += b.w * b.w;
    vmx.x = fmaxf(vmx.x, b.x); vmx.y = fmaxf(vmx.y, b.y);
    vmx.z = fmaxf(vmx.z, b.z); vmx.w = fmaxf(vmx.w, b.w);
    vmn.x = fminf(vmn.x, b.x); vmn.y = fminf(vmn.y, b.y);
    vmn.z = fminf(vmn.z, b.z); vmn.w = fminf(vmn.w, b.w);

    float dinv = 1.0f / ((float)(end - beg) + 1.0f);
    float4 mean = make_float4(vs.x * dinv, vs.y * dinv, vs.z * dinv, vs.w * dinv);
    float4 sqm  = make_float4(vq.x * dinv, vq.y * dinv, vq.z * dinv, vq.w * dinv);
    float4 stdv;
    stdv.x = sqrtf(fmaxf(sqm.x - mean.x * mean.x, 1e-6f));
    stdv.y = sqrtf(fmaxf(sqm.y - mean.y * mean.y, 1e-6f));
    stdv.z = sqrtf(fmaxf(sqm.z - mean.z * mean.z, 1e-6f));
    stdv.w = sqrtf(fmaxf(sqm.w - mean.w * mean.w, 1e-6f));

    float4* f = reinterpret_cast<float4*>(g_feats);
    f[(0 * N_NODES + gw) * 32 + lane] = mean;
    f[(1 * N_NODES + gw) * 32 + lane] = vmx;
    f[(2 * N_NODES + gw) * 32 + lane] = vmn;
    f[(3 * N_NODES + gw) * 32 + lane] = stdv;
}

// ---------------- tf32 tensor-core GEMM + LN + ReLU + residual --------------
// C[50000,128] = A[50000,1664] @ W[1664,128]; A built on the fly.
// 128x128 block tile, 8 warps (2x4), warp tile 64x32, mma.m16n8k8.tf32.
__global__ void __launch_bounds__(256, 2)
k_gemm(const float* __restrict__ W, const float* __restrict__ bias,
       const float* __restrict__ lng, const float* __restrict__ lnb,
       const float* __restrict__ xin) {
    __shared__ float As[2][128 * ASTR];   // m-major, k permuted within 8-groups
    __shared__ float Bs[2][BK * BSTR];    // k-major [k][n]
    __shared__ float redS[128][4];
    __shared__ float redQ[128][4];

    int tid  = threadIdx.x;
    int lane = tid & 31, wid = tid >> 5;
    int wm = wid & 1, wn = wid >> 1;      // warp grid 2(m) x 4(n)
    int q = lane >> 2, p = lane & 3;
    int row0 = blockIdx.x * 128;

    // A loader: thread -> (row am, k-half ak in {0,8})
    int am = tid >> 1;
    int ak = (tid & 1) * 8;
    int grow = row0 + am;
    bool rok = grow < N_NODES;
    float sS = rok ? g_scaleS[grow] : 1.0f;
    float fac1 = sS, fac2 = 1.0f / fmaxf(sS, 1e-2f);
    // B loader: thread -> (bk, bn)
    int bk = tid >> 4, bn = (tid & 15) * 8;

    float acc[4][4][4];
#pragma unroll
    for (int i = 0; i < 4; i++)
#pragma unroll
        for (int j = 0; j < 4; j++)
#pragma unroll
            for (int c = 0; c < 4; c++) acc[i][j][c] = 0.0f;

    float ah[8];

    auto loadA = [&](int kt) {
        int kb   = kt * BK;
        int bblk = kb >> 7;               // 0..12, uniform
        int kc   = (kb & 127) + ak;
        if (rok) {
            const float* ptr;
            float fac;
            if (bblk < 12) {
                ptr = g_feats + ((bblk & 3) * N_NODES + grow) * 128 + kc;
                int jj = bblk >> 2;
                fac = (jj == 0) ? 1.0f : ((jj == 1) ? fac1 : fac2);
            } else {
                ptr = xin + grow * 128 + kc;
                fac = 1.0f;
            }
            float4 v0 = *reinterpret_cast<const float4*>(ptr);
            float4 v1 = *reinterpret_cast<const float4*>(ptr + 4);
            ah[0] = v0.x * fac; ah[1] = v0.y * fac; ah[2] = v0.z * fac; ah[3] = v0.w * fac;
            ah[4] = v1.x * fac; ah[5] = v1.y * fac; ah[6] = v1.z * fac; ah[7] = v1.w * fac;
        } else {
#pragma unroll
            for (int i = 0; i < 8; i++) ah[i] = 0.0f;
        }
    };

    // permuted store: phys j <- logical k: j = (k&3)*2 + (k>>2)
    auto stsA = [&](int buf) {
        float t[8];
#pragma unroll
        for (int i = 0; i < 8; i++) t[i] = f2tf(ah[i]);
        float* dst = &As[buf][am * ASTR + ak];
        *reinterpret_cast<float4*>(dst)     = make_float4(t[0], t[4], t[1], t[5]);
        *reinterpret_cast<float4*>(dst + 4) = make_float4(t[2], t[6], t[3], t[7]);
    };

    auto cpB = [&](int kt, int buf) {
        const float* wp = W + (kt * BK + bk) * 128 + bn;
        uint32_t d0 = (uint32_t)__cvta_generic_to_shared(&Bs[buf][bk * BSTR + bn]);
        asm volatile("cp.async.ca.shared.global [%0], [%1], 16;\n" :: "r"(d0), "l"(wp));
        asm volatile("cp.async.ca.shared.global [%0], [%1], 16;\n" :: "r"(d0 + 16), "l"(wp + 4));
    };

    // prologue
    loadA(0);
    cpB(0, 0);
    stsA(0);
    asm volatile("cp.async.commit_group;\n");
    asm volatile("cp.async.wait_group 0;\n");
    __syncthreads();

#pragma unroll 1
    for (int kt = 0; kt < NKT; kt++) {
        int buf = kt & 1;
        if (kt + 1 < NKT) {
            loadA(kt + 1);
            cpB(kt + 1, buf ^ 1);
            asm volatile("cp.async.commit_group;\n");
        }

#pragma unroll
        for (int h = 0; h < 2; h++) {
            int koff = h * 8;
            uint32_t a[4][4], b[4][2];
#pragma unroll
            for (int mt = 0; mt < 4; mt++) {
                int ra = wm * 64 + mt * 16 + q;
                float2 t0 = *reinterpret_cast<const float2*>(&As[buf][ra * ASTR + koff + 2 * p]);
                float2 t1 = *reinterpret_cast<const float2*>(&As[buf][(ra + 8) * ASTR + koff + 2 * p]);
                a[mt][0] = __float_as_uint(t0.x);
                a[mt][1] = __float_as_uint(t1.x);
                a[mt][2] = __float_as_uint(t0.y);
                a[mt][3] = __float_as_uint(t1.y);
            }
#pragma unroll
            for (int nt = 0; nt < 4; nt++) {
                int nc = wn * 32 + nt * 8 + q;
                b[nt][0] = __float_as_uint(Bs[buf][(koff + p) * BSTR + nc]);
                b[nt][1] = __float_as_uint(Bs[buf][(koff + p + 4) * BSTR + nc]);
            }
#pragma unroll
            for (int mt = 0; mt < 4; mt++)
#pragma unroll
                for (int nt = 0; nt < 4; nt++)
                    asm volatile(
                        "mma.sync.aligned.m16n8k8.row.col.f32.tf32.tf32.f32 "
                        "{%0,%1,%2,%3}, {%4,%5,%6,%7}, {%8,%9}, {%0,%1,%2,%3};"
                        : "+f"(acc[mt][nt][0]), "+f"(acc[mt][nt][1]),
                          "+f"(acc[mt][nt][2]), "+f"(acc[mt][nt][3])
                        : "r"(a[mt][0]), "r"(a[mt][1]), "r"(a[mt][2]), "r"(a[mt][3]),
                          "r"(b[nt][0]), "r"(b[nt][1]));
        }

        if (kt + 1 < NKT) {
            stsA(buf ^ 1);
            asm volatile("cp.async.wait_group 0;\n");
            __syncthreads();
        }
    }

    // ---- epilogue: bias + LN + ReLU + residual ----
    float2 bias2[4], lng2[4], lnb2[4];
#pragma unroll
    for (int nt = 0; nt < 4; nt++) {
        int c = wn * 32 + nt * 8 + 2 * p;
        bias2[nt] = *reinterpret_cast<const float2*>(bias + c);
        lng2[nt]  = *reinterpret_cast<const float2*>(lng + c);
        lnb2[nt]  = *reinterpret_cast<const float2*>(lnb + c);
    }

    // partial row sums (this warp's 32 cols), reduce over p-lanes, stash in smem
#pragma unroll
    for (int mt = 0; mt < 4; mt++) {
        float sA = 0.f, qA = 0.f, sB = 0.f, qB = 0.f;
#pragma unroll
        for (int nt = 0; nt < 4; nt++) {
            float v0 = acc[mt][nt][0] + bias2[nt].x;
            float v1 = acc[mt][nt][1] + bias2[nt].y;
            float v2 = acc[mt][nt][2] + bias2[nt].x;
            float v3 = acc[mt][nt][3] + bias2[nt].y;
            sA += v0 + v1; qA += v0 * v0 + v1 * v1;
            sB += v2 + v3; qB += v2 * v2 + v3 * v3;
        }
#pragma unroll
        for (int m = 1; m < 4; m <<= 1) {
            sA += __shfl_xor_sync(0xffffffffu, sA, m);
            qA += __shfl_xor_sync(0xffffffffu, qA, m);
            sB += __shfl_xor_sync(0xffffffffu, sB, m);
            qB += __shfl_xor_sync(0xffffffffu, qB, m);
        }
        if (p == 0) {
            int rA = wm * 64 + mt * 16 + q;
            redS[rA][wn] = sA; redQ[rA][wn] = qA;
            redS[rA + 8][wn] = sB; redQ[rA + 8][wn] = qB;
        }
    }
    __syncthreads();

#pragma unroll
    for (int mt = 0; mt < 4; mt++) {
#pragma unroll
        for (int half = 0; half < 2; half++) {
            int rloc = wm * 64 + mt * 16 + q + half * 8;
            int r = row0 + rloc;
            float s = redS[rloc][0] + redS[rloc][1] + redS[rloc][2] + redS[rloc][3];
            float sq = redQ[rloc][0] + redQ[rloc][1] + redQ[rloc][2] + redQ[rloc][3];
            float mu = s * (1.0f / 128.0f);
            float var = sq * (1.0f / 128.0f) - mu * mu;
            float rstd = rsqrtf(var + 1e-5f);
            if (r < N_NODES) {
#pragma unroll
                for (int nt = 0; nt < 4; nt++) {
                    int c = wn * 32 + nt * 8 + 2 * p;
                    float v0 = acc[mt][nt][half * 2 + 0] + bias2[nt].x;
                    float v1 = acc[mt][nt][half * 2 + 1] + bias2[nt].y;
                    float o0 = fmaxf((v0 - mu) * rstd * lng2[nt].x + lnb2[nt].x, 0.0f);
                    float o1 = fmaxf((v1 - mu) * rstd * lng2[nt].y + lnb2[nt].y, 0.0f);
                    float2 xr = *reinterpret_cast<const float2*>(xin + r * 128 + c);
                    *reinterpret_cast<float2*>(g_x + r * 128 + c) =
                        make_float2(o0 + xr.x, o1 + xr.y);
                }
            }
        }
    }
}

// ---------------- distmult scoring (warp per triple) ------------------------
__global__ void k_score(const int* __restrict__ src, const int* __restrict__ rel,
                        const int* __restrict__ dst, const float* __restrict__ qw,
                        float* __restrict__ out) {
    int gw   = (blockIdx.x * blockDim.x + threadIdx.x) >> 5;
    int lane = threadIdx.x & 31;
    if (gw >= 1024 * 32) return;
    int s = __ldg(src + gw), r = __ldg(rel + gw), d = __ldg(dst + gw);
    const float4* xv = reinterpret_cast<const float4*>(g_x);
    float4 a = __ldg(xv + s * 32 + lane);
    float4 qq = __ldg(reinterpret_cast<const float4*>(qw) + r * 32 + lane);
    float4 c = __ldg(xv + d * 32 + lane);
    float pr = a.x * qq.x * c.x + a.y * qq.y * c.y + a.z * qq.z * c.z + a.w * qq.w * c.w;
#pragma unroll
    for (int m = 16; m > 0; m >>= 1) pr += __shfl_xor_sync(0xffffffffu, pr, m);
    if (lane == 0) out[gw] = pr;
}

// ---------------- launcher ---------------------------------------------------
extern "C" void kernel_launch(void* const* d_in, const int* in_sizes, int n_in,
                              void* d_out, int out_size) {
    const float* x0    = (const float*)d_in[0];
    const int*   eidx  = (const int*)  d_in[1];
    const int*   etype = (const int*)  d_in[2];
    const float* ew    = (const float*)d_in[3];
    const float* relw  = (const float*)d_in[4];
    const float* linw  = (const float*)d_in[5];
    const float* linb  = (const float*)d_in[6];
    const float* lng   = (const float*)d_in[7];
    const float* lnb   = (const float*)d_in[8];
    const float* qw    = (const float*)d_in[9];
    const int*   src   = (const int*)  d_in[10];
    const int*   rel   = (const int*)  d_in[11];
    const int*   dst   = (const int*)  d_in[12];
    float*       out   = (float*)d_out;

    const int* esrc = eidx;
    const int* edst = eidx + N_EDGES;

    float* gx;
    cudaGetSymbolAddress((void**)&gx, g_x);
    float* gW;
    cudaGetSymbolAddress((void**)&gW, g_W);

    k_cvtW<<<(4 * KDIM * DIM + 255) / 256, 256>>>(linw);
    k_zero<<<(N_NODES + 255) / 256, 256>>>();
    k_hist<<<(N_EDGES + 255) / 256, 256>>>(edst);
    k_scan<<<1, 1024>>>();
    k_fill<<<(N_EDGES + 255) / 256, 256>>>(esrc, edst, etype, ew);

    for (int l = 0; l < 4; l++) {
        const float* xin = (l == 0) ? x0 : gx;
        k_agg<<<(N_NODES * 32 + 255) / 256, 256>>>(xin, x0, relw + l * N_REL * DIM);
        k_gemm<<<(N_NODES + 127) / 128, 256>>>(gW + l * KDIM * DIM,
                                               linb + l * DIM,
                                               lng + l * DIM,
                                               lnb + l * DIM,
                                               xin);
    }

    k_score<<<(1024 * 32 * 32 + 255) / 256, 256>>>(src, rel, dst, qw, out);
}